// round 9
// baseline (speedup 1.0000x reference)
#include <cuda_runtime.h>
#include <cuda_fp16.h>
#include <cstdint>

// ---------------- problem constants ----------------
#define LNUM 8
#define BNUM 1024
#define DNUM 1024
#define FNUM 8192
#define KC   32              // fp32 K elements per chunk

static const long long FEATS_OFF = (long long)LNUM * BNUM * DNUM;               // 8388608
static const long long LOSS_OFF  = FEATS_OFF + (long long)LNUM * BNUM * FNUM;   // 75497472

// ---------------- global accumulators ----------------
__device__ double g_sp_sum;
__device__ double g_sq_sum;
__device__ unsigned long long g_cnt[LNUM];

__global__ void init_acc_kernel() {
    g_sp_sum = 0.0;
    g_sq_sum = 0.0;
    for (int i = 0; i < LNUM; ++i) g_cnt[i] = 0ull;
}

// ---------------- small helpers ----------------
__device__ __forceinline__ uint32_t smem_u32(const void* p) {
    uint32_t a;
    asm("{ .reg .u64 t; cvta.to.shared.u64 t, %1; cvt.u32.u64 %0, t; }" : "=r"(a) : "l"(p));
    return a;
}
__device__ __forceinline__ void lds128(uint32_t (&r)[4], uint32_t addr) {
    asm volatile("ld.shared.v4.b32 {%0,%1,%2,%3}, [%4];"
        : "=r"(r[0]), "=r"(r[1]), "=r"(r[2]), "=r"(r[3]) : "r"(addr));
}
__device__ __forceinline__ void mma16816(float (&c)[4], const uint32_t (&a)[4],
                                         uint32_t b0, uint32_t b1) {
    asm volatile("mma.sync.aligned.m16n8k16.row.col.f32.f16.f16.f32 "
        "{%0,%1,%2,%3}, {%4,%5,%6,%7}, {%8,%9}, {%0,%1,%2,%3};"
        : "+f"(c[0]), "+f"(c[1]), "+f"(c[2]), "+f"(c[3])
        : "r"(a[0]), "r"(a[1]), "r"(a[2]), "r"(a[3]), "r"(b0), "r"(b1));
}
// split (x, y) -> hi f16x2 (x in low half) and lo f16x2 (residual)
__device__ __forceinline__ void split2(float x, float y, uint32_t& h, uint32_t& l) {
    asm("cvt.rn.f16x2.f32 %0, %1, %2;" : "=r"(h) : "f"(y), "f"(x));
    float fx, fy;
    asm("{ .reg .f16 a, b; mov.b32 {a, b}, %2; cvt.f32.f16 %0, a; cvt.f32.f16 %1, b; }"
        : "=f"(fx), "=f"(fy) : "r"(h));
    float lx = x - fx, ly = y - fy;
    asm("cvt.rn.f16x2.f32 %0, %1, %2;" : "=r"(l) : "f"(ly), "f"(lx));
}
__device__ __forceinline__ uint32_t pack16(float x, float y) {
    uint32_t h;
    asm("cvt.rn.f16x2.f32 %0, %1, %2;" : "=r"(h) : "f"(y), "f"(x));
    return h;
}

// ---------------- GEMM mainloop: 256x128 tile, 512 threads, 2-term ----------------
// C[256,128] += sum over segments of A_seg[256, kdim] * B_seg[128, kdim]^T
// smem stage (u32 words): [Ah 4096 | Bh 2048 | Bl 2048] = 8192 words (32 KB), x2 stages.
// A hi plane: 16 mtiles x 2 kt blocks of 128 words. B planes: 16 ntiles x 128 words.
template <int CPS>   // chunks per segment (kdim / KC)
__device__ __forceinline__ void run_gemm(uint32_t* smp, uint32_t smb,
                                         const float* A0, const float* A1, const float* A2,
                                         const float* B0, const float* B1, const float* B2,
                                         int nseg, const int kdim, float (&acc)[4][4][4]) {
    constexpr int STW = 8192;
    constexpr int BH = 4096, BL = 6144;

    const int tid  = threadIdx.x;
    const int lane = tid & 31;
    const int wid  = tid >> 5;        // 0..15
    const int wm   = wid >> 2;        // 0..3 (64-row band)
    const int wn   = wid & 3;         // 0..3 (32-col band)
    const int rbase = tid >> 4;       // 0..31
    const int pc    = tid & 15;       // float2 pair within KC
    const int kt_p  = pc >> 3, kk = pc & 7, tt = kk & 3, kh = kk >> 2;

    // A: 8 rows/thread (rows rbase + 32*i, i<8 -> 256 rows)
    int aslot[8], agoff[8];
#pragma unroll
    for (int i = 0; i < 8; ++i) {
        const int row = rbase + 32 * i;
        const int mt = row >> 4, rm = row & 15, g = rm & 7, rh = rm >> 3;
        aslot[i] = ((mt * 2 + kt_p) << 7) + ((g * 4 + tt) << 2) + (rh + 2 * kh);
        agoff[i] = row * kdim + 2 * pc;
    }
    // B: 4 rows/thread (rows rbase + 32*i, i<4 -> 128 rows)
    int bslot[4], bgoff[4];
#pragma unroll
    for (int i = 0; i < 4; ++i) {
        const int row = rbase + 32 * i;
        const int nt = row >> 3, gn = row & 7;
        bslot[i] = (nt << 7) + ((gn * 4 + tt) << 2) + kt_p * 2 + kh;
        bgoff[i] = row * kdim + 2 * pc;
    }

    const int NC = nseg * CPS;
    float2 av[8], bv[4];
#pragma unroll
    for (int i = 0; i < 8; ++i) av[i] = *(const float2*)(A0 + agoff[i]);
#pragma unroll
    for (int i = 0; i < 4; ++i) bv[i] = *(const float2*)(B0 + bgoff[i]);

    for (int c = 0; c < NC; ++c) {
        const int s = c & 1;
        uint32_t* st = smp + s * STW;
#pragma unroll
        for (int i = 0; i < 8; ++i) {
            st[aslot[i]] = pack16(av[i].x, av[i].y);   // A hi only (2-term)
        }
#pragma unroll
        for (int i = 0; i < 4; ++i) {
            uint32_t h, l;
            split2(bv[i].x, bv[i].y, h, l);
            st[BH + bslot[i]] = h;
            st[BL + bslot[i]] = l;
        }
        if (c + 1 < NC) {
            const int cn = c + 1;
            const int seg = cn / CPS, kc = cn % CPS;
            const float* An = (seg == 0) ? A0 : ((seg == 1) ? A1 : A2);
            const float* Bn = (seg == 0) ? B0 : ((seg == 1) ? B1 : B2);
            An += kc * KC;
            Bn += kc * KC;
#pragma unroll
            for (int i = 0; i < 8; ++i) av[i] = *(const float2*)(An + agoff[i]);
#pragma unroll
            for (int i = 0; i < 4; ++i) bv[i] = *(const float2*)(Bn + bgoff[i]);
        }
        __syncthreads();

        const uint32_t base = smb + s * (STW * 4);
        uint32_t bh[4][4], bl[4][4];
#pragma unroll
        for (int n = 0; n < 4; ++n) {
            const uint32_t boff = ((wn * 4 + n) << 9) + lane * 16;
            lds128(bh[n], base + BH * 4 + boff);
            lds128(bl[n], base + BL * 4 + boff);
        }
#pragma unroll
        for (int kt = 0; kt < 2; ++kt) {
            uint32_t ah[4][4];
#pragma unroll
            for (int m = 0; m < 4; ++m) {
                const int mt = wm * 4 + m;                       // 0..15
                const uint32_t aoff = (((mt * 2) + kt) << 9) + lane * 16;
                lds128(ah[m], base + aoff);
            }
            // term hh (16 independent accumulators)
#pragma unroll
            for (int m = 0; m < 4; ++m)
#pragma unroll
                for (int n = 0; n < 4; ++n)
                    mma16816(acc[m][n], ah[m], bh[n][kt * 2], bh[n][kt * 2 + 1]);
            // term hl
#pragma unroll
            for (int m = 0; m < 4; ++m)
#pragma unroll
                for (int n = 0; n < 4; ++n)
                    mma16816(acc[m][n], ah[m], bl[n][kt * 2], bl[n][kt * 2 + 1]);
        }
        __syncthreads();
    }
}

// ---------------- encoder (256x128 tile, 512 threads) ----------------
__global__ __launch_bounds__(512) void encoder_mma(const float* __restrict__ resid,  // [L,B,D]
                                                   const float* __restrict__ enc_w,  // [L,F,D]
                                                   const float* __restrict__ enc_b,  // [L,F]
                                                   float* __restrict__ out) {
    extern __shared__ uint32_t smraw[];
    __shared__ float sbias[128];
    __shared__ float s_sp[16];
    __shared__ int   s_cnt[16];

    const int tid = threadIdx.x;
    const int l   = blockIdx.z;
    const int m0  = blockIdx.y * 256;
    const int n0  = blockIdx.x * 128;

    if (tid < 128) sbias[tid] = enc_b[(long long)l * FNUM + n0 + tid];

    float acc[4][4][4];
#pragma unroll
    for (int m = 0; m < 4; ++m)
#pragma unroll
        for (int n = 0; n < 4; ++n)
#pragma unroll
            for (int q = 0; q < 4; ++q) acc[m][n][q] = 0.0f;

    const float* A = resid + ((long long)l * BNUM + m0) * DNUM;
    const float* W = enc_w + ((long long)l * FNUM + n0) * DNUM;
    run_gemm<DNUM / KC>(smraw, smem_u32(smraw), A, A, A, W, W, W, 1, DNUM, acc);

    const int lane = tid & 31, wid = tid >> 5;
    const int wm = wid >> 2, wn = wid & 3;
    const int g = lane >> 2, tt = lane & 3;

    float sp = 0.0f;
    int   cnt = 0;
#pragma unroll
    for (int m = 0; m < 4; ++m) {
        const int r0 = m0 + wm * 64 + m * 16 + g;
#pragma unroll
        for (int n = 0; n < 4; ++n) {
            const int cl  = wn * 32 + n * 8 + tt * 2;
            const float b0 = sbias[cl], b1 = sbias[cl + 1];
            float x0 = fmaxf(acc[m][n][0] + b0, 0.0f);
            float x1 = fmaxf(acc[m][n][1] + b1, 0.0f);
            float x2 = fmaxf(acc[m][n][2] + b0, 0.0f);
            float x3 = fmaxf(acc[m][n][3] + b1, 0.0f);
            sp  += (x0 + x1) + (x2 + x3);
            cnt += (x0 > 0.0f) + (x1 > 0.0f) + (x2 > 0.0f) + (x3 > 0.0f);
            float* p0 = out + FEATS_OFF + ((long long)l * BNUM + r0) * FNUM + n0 + cl;
            float* p1 = out + FEATS_OFF + ((long long)l * BNUM + r0 + 8) * FNUM + n0 + cl;
            *(float2*)p0 = make_float2(x0, x1);
            *(float2*)p1 = make_float2(x2, x3);
        }
    }
#pragma unroll
    for (int o = 16; o > 0; o >>= 1) {
        sp  += __shfl_down_sync(0xffffffffu, sp, o);
        cnt += __shfl_down_sync(0xffffffffu, cnt, o);
    }
    if (lane == 0) { s_sp[wid] = sp; s_cnt[wid] = cnt; }
    __syncthreads();
    if (tid == 0) {
        float tsp = 0.0f; int tc = 0;
        for (int w = 0; w < 16; ++w) { tsp += s_sp[w]; tc += s_cnt[w]; }
        atomicAdd(&g_sp_sum, (double)tsp);
        atomicAdd(&g_cnt[l], (unsigned long long)tc);
    }
}

// ---------------- decoder (256x128 tile, 512 threads; t descending) ----------------
__global__ __launch_bounds__(512) void decoder_mma(const float* __restrict__ feats,  // [L,B,F]
                                                   const float* __restrict__ dec_w,  // [P,D,F]
                                                   const float* __restrict__ tgt,    // [L,B,D]
                                                   float* __restrict__ out) {
    extern __shared__ uint32_t smraw[];
    __shared__ float s_sq[16];

    const int tid = threadIdx.x;
    const int bid = blockIdx.x;
    const int t   = 7 - (bid >> 5);
    const int rem = bid & 31;
    const int m0  = (rem >> 3) * 256;
    const int n0  = (rem & 7) * 128;

    float acc[4][4][4];
#pragma unroll
    for (int m = 0; m < 4; ++m)
#pragma unroll
        for (int n = 0; n < 4; ++n)
#pragma unroll
            for (int q = 0; q < 4; ++q) acc[m][n][q] = 0.0f;

    const int s_lo = (t >= 2) ? (t - 2) : 0;
    const int nseg = t - s_lo + 1;
    const float* As[3]; const float* Bs[3];
#pragma unroll
    for (int i = 0; i < 3; ++i) {
        const int s    = (s_lo + i <= t) ? (s_lo + i) : t;
        const int base = (s <= 5) ? (3 * s) : (2 * s + 6);
        const int p    = base + (t - s);
        As[i] = feats + ((long long)s * BNUM + m0) * FNUM;
        Bs[i] = dec_w + ((long long)p * DNUM + n0) * FNUM;
    }
    run_gemm<FNUM / KC>(smraw, smem_u32(smraw), As[0], As[1], As[2],
                        Bs[0], Bs[1], Bs[2], nseg, FNUM, acc);

    const int lane = tid & 31, wid = tid >> 5;
    const int wm = wid >> 2, wn = wid & 3;
    const int g = lane >> 2, tt = lane & 3;

    float sq = 0.0f;
#pragma unroll
    for (int m = 0; m < 4; ++m) {
        const int r0 = m0 + wm * 64 + m * 16 + g;
#pragma unroll
        for (int n = 0; n < 4; ++n) {
            const int col = n0 + wn * 32 + n * 8 + tt * 2;
            const long long row0 = (long long)t * BNUM + r0;
            const long long row1 = row0 + 8;
            float2 t0 = *(const float2*)(tgt + row0 * DNUM + col);
            float2 t1 = *(const float2*)(tgt + row1 * DNUM + col);
            const float v0 = acc[m][n][0], v1 = acc[m][n][1];
            const float v2 = acc[m][n][2], v3 = acc[m][n][3];
            float d0 = v0 - t0.x, d1 = v1 - t0.y, d2 = v2 - t1.x, d3 = v3 - t1.y;
            sq = fmaf(d0, d0, sq); sq = fmaf(d1, d1, sq);
            sq = fmaf(d2, d2, sq); sq = fmaf(d3, d3, sq);
            *(float2*)(out + row0 * DNUM + col) = make_float2(v0, v1);
            *(float2*)(out + row1 * DNUM + col) = make_float2(v2, v3);
        }
    }
#pragma unroll
    for (int o = 16; o > 0; o >>= 1) sq += __shfl_down_sync(0xffffffffu, sq, o);
    if (lane == 0) s_sq[wid] = sq;
    __syncthreads();
    if (tid == 0) {
        float tsq = 0.0f;
        for (int w = 0; w < 16; ++w) tsq += s_sq[w];
        atomicAdd(&g_sq_sum, (double)tsq);
    }
}

// ---------------- finalize scalars ----------------
__global__ void finalize_kernel(float* __restrict__ out) {
    const int tid = threadIdx.x;
    if (tid == 0) {
        double rl = g_sq_sum / ((double)LNUM * (double)BNUM * (double)DNUM);
        double sl = 1e-4 * (g_sp_sum / ((double)LNUM * (double)BNUM * (double)FNUM));
        out[LOSS_OFF + 0] = (float)(rl + sl);
        out[LOSS_OFF + 1] = (float)rl;
        out[LOSS_OFF + 2] = (float)sl;
    }
    if (tid < LNUM) out[LOSS_OFF + 3 + tid] = (float)((double)g_cnt[tid] / (double)BNUM);
}

// ---------------- entry point ----------------
#define SMEM_DYN (2 * 8192 * 4)   // 64 KB (two 32 KB stages)

extern "C" void kernel_launch(void* const* d_in, const int* in_sizes, int n_in,
                              void* d_out, int out_size) {
    (void)in_sizes; (void)n_in; (void)out_size;
    const float* resid   = (const float*)d_in[0];
    const float* targets = (const float*)d_in[1];
    const float* enc_w   = (const float*)d_in[2];
    const float* enc_b   = (const float*)d_in[3];
    const float* dec_w   = (const float*)d_in[4];
    float* out = (float*)d_out;

    static bool attr_done = false;
    if (!attr_done) {
        cudaFuncSetAttribute(encoder_mma, cudaFuncAttributeMaxDynamicSharedMemorySize, SMEM_DYN);
        cudaFuncSetAttribute(decoder_mma, cudaFuncAttributeMaxDynamicSharedMemorySize, SMEM_DYN);
        attr_done = true;
    }

    init_acc_kernel<<<1, 1>>>();

    dim3 genc(FNUM / 128, BNUM / 256, LNUM);  // (64, 4, 8)
    encoder_mma<<<genc, 512, SMEM_DYN>>>(resid, enc_w, enc_b, out);

    decoder_mma<<<256, 512, SMEM_DYN>>>(out + FEATS_OFF, dec_w, targets, out);

    finalize_kernel<<<1, 32>>>(out);
}

// round 10
// speedup vs baseline: 1.7388x; 1.7388x over previous
#include <cuda_runtime.h>
#include <cuda_fp16.h>
#include <cstdint>

// ---------------- problem constants ----------------
#define LNUM 8
#define BNUM 1024
#define DNUM 1024
#define FNUM 8192
#define KC   32              // fp32 K elements per chunk

static const long long FEATS_OFF = (long long)LNUM * BNUM * DNUM;               // 8388608
static const long long LOSS_OFF  = FEATS_OFF + (long long)LNUM * BNUM * FNUM;   // 75497472

// ---------------- global accumulators ----------------
__device__ double g_sp_sum;
__device__ double g_sq_sum;
__device__ unsigned long long g_cnt[LNUM];

__global__ void init_acc_kernel() {
    g_sp_sum = 0.0;
    g_sq_sum = 0.0;
    for (int i = 0; i < LNUM; ++i) g_cnt[i] = 0ull;
}

// ---------------- small helpers ----------------
__device__ __forceinline__ uint32_t smem_u32(const void* p) {
    uint32_t a;
    asm("{ .reg .u64 t; cvta.to.shared.u64 t, %1; cvt.u32.u64 %0, t; }" : "=r"(a) : "l"(p));
    return a;
}
__device__ __forceinline__ void lds128(uint32_t (&r)[4], uint32_t addr) {
    asm volatile("ld.shared.v4.b32 {%0,%1,%2,%3}, [%4];"
        : "=r"(r[0]), "=r"(r[1]), "=r"(r[2]), "=r"(r[3]) : "r"(addr));
}
__device__ __forceinline__ void mma16816(float (&c)[4], const uint32_t (&a)[4],
                                         uint32_t b0, uint32_t b1) {
    asm volatile("mma.sync.aligned.m16n8k16.row.col.f32.f16.f16.f32 "
        "{%0,%1,%2,%3}, {%4,%5,%6,%7}, {%8,%9}, {%0,%1,%2,%3};"
        : "+f"(c[0]), "+f"(c[1]), "+f"(c[2]), "+f"(c[3])
        : "r"(a[0]), "r"(a[1]), "r"(a[2]), "r"(a[3]), "r"(b0), "r"(b1));
}
// split (x, y) -> hi f16x2 (x in low half) and lo f16x2 (residual)
__device__ __forceinline__ void split2(float x, float y, uint32_t& h, uint32_t& l) {
    asm("cvt.rn.f16x2.f32 %0, %1, %2;" : "=r"(h) : "f"(y), "f"(x));
    float fx, fy;
    asm("{ .reg .f16 a, b; mov.b32 {a, b}, %2; cvt.f32.f16 %0, a; cvt.f32.f16 %1, b; }"
        : "=f"(fx), "=f"(fy) : "r"(h));
    float lx = x - fx, ly = y - fy;
    asm("cvt.rn.f16x2.f32 %0, %1, %2;" : "=r"(l) : "f"(ly), "f"(lx));
}
__device__ __forceinline__ uint32_t pack16(float x, float y) {
    uint32_t h;
    asm("cvt.rn.f16x2.f32 %0, %1, %2;" : "=r"(h) : "f"(y), "f"(x));
    return h;
}

// ---------------- consumer: one K=32 chunk, 2-term (hh + hl) ----------------
// stage (u32 words): [Ah 2048 | Bh 2048 | Bl 2048] = 6144 words (24 KB)
__device__ __forceinline__ void consume_chunk2(uint32_t base, int lane, int wm, int wn,
                                               float (&acc)[4][4][4]) {
    uint32_t bh[4][4], bl[4][4];
#pragma unroll
    for (int n = 0; n < 4; ++n) {
        const uint32_t boff = ((wn * 4 + n) << 9) + lane * 16;
        lds128(bh[n], base + 2048 * 4 + boff);
        lds128(bl[n], base + 4096 * 4 + boff);
    }
#pragma unroll
    for (int kt = 0; kt < 2; ++kt) {
        uint32_t ah[4][4];
#pragma unroll
        for (int m = 0; m < 4; ++m) {
            const uint32_t aoff = ((((wm * 4 + m) * 2) + kt) << 9) + lane * 16;
            lds128(ah[m], base + aoff);
        }
#pragma unroll
        for (int m = 0; m < 4; ++m)
#pragma unroll
            for (int n = 0; n < 4; ++n)
                mma16816(acc[m][n], ah[m], bh[n][kt * 2], bh[n][kt * 2 + 1]);
#pragma unroll
        for (int m = 0; m < 4; ++m)
#pragma unroll
            for (int n = 0; n < 4; ++n)
                mma16816(acc[m][n], ah[m], bl[n][kt * 2], bl[n][kt * 2 + 1]);
    }
}

// producer slot bases: aslot[i] = aslot0 + 256*i, bslot[i] = bslot0 + 256*i
__device__ __forceinline__ void prod_bases(int tid, int& aslot0, int& bslot0, int& goff0_pc) {
    const int rbase = tid >> 4;       // 0..15
    const int pc    = tid & 15;
    const int kt_p  = pc >> 3, kk = pc & 7, tt = kk & 3, kh = kk >> 2;
    const int g = rbase & 7, rh = rbase >> 3;
    aslot0 = (kt_p << 7) + ((g * 4 + tt) << 2) + (rh + 2 * kh);
    bslot0 = (rh << 7) + ((g * 4 + tt) << 2) + kt_p * 2 + kh;   // nt=rbase>>3=rh, gn=g
    goff0_pc = 2 * pc;                // add rbase*kdim at call site
}

// ---------------- encoder (128x128 tile, 256 threads, occ 2) ----------------
__global__ __launch_bounds__(256, 2) void encoder_mma(const float* __restrict__ resid,  // [L,B,D]
                                                      const float* __restrict__ enc_w,  // [L,F,D]
                                                      const float* __restrict__ enc_b,  // [L,F]
                                                      float* __restrict__ out) {
    extern __shared__ uint32_t smraw[];
    __shared__ float sbias[128];
    __shared__ float s_sp[8];
    __shared__ int   s_cnt[8];

    const int tid = threadIdx.x;
    const int l   = blockIdx.z;
    const int m0  = blockIdx.y * 128;
    const int n0  = blockIdx.x * 128;
    const uint32_t smb = smem_u32(smraw);

    if (tid < 128) sbias[tid] = enc_b[(long long)l * FNUM + n0 + tid];

    int aslot0, bslot0, gpc;
    prod_bases(tid, aslot0, bslot0, gpc);
    const int rbase = tid >> 4;
    const float* Ap = resid + ((long long)l * BNUM + m0 + rbase) * DNUM + gpc;
    const float* Bp = enc_w + ((long long)l * FNUM + n0 + rbase) * DNUM + gpc;

    float acc[4][4][4];
#pragma unroll
    for (int m = 0; m < 4; ++m)
#pragma unroll
        for (int n = 0; n < 4; ++n)
#pragma unroll
            for (int q = 0; q < 4; ++q) acc[m][n][q] = 0.0f;

    const int lane = tid & 31, wid = tid >> 5;
    const int wm = wid >> 2, wn = wid & 3;

    for (int c = 0; c < 32; ++c) {
        uint32_t* st = smraw + (c & 1) * 6144;
#pragma unroll
        for (int i = 0; i < 8; ++i) {
            float2 v = *(const float2*)(Ap + i * 16 * DNUM);
            st[aslot0 + 256 * i] = pack16(v.x, v.y);
        }
#pragma unroll
        for (int i = 0; i < 8; ++i) {
            float2 v = *(const float2*)(Bp + i * 16 * DNUM);
            uint32_t h, lo;
            split2(v.x, v.y, h, lo);
            st[2048 + bslot0 + 256 * i] = h;
            st[4096 + bslot0 + 256 * i] = lo;
        }
        Ap += KC;
        Bp += KC;
        __syncthreads();
        consume_chunk2(smb + (c & 1) * 24576, lane, wm, wn, acc);
    }

    const int g = lane >> 2, tt = lane & 3;

    float sp = 0.0f;
    int   cnt = 0;
#pragma unroll
    for (int m = 0; m < 4; ++m) {
        const int r0 = m0 + wm * 64 + m * 16 + g;
#pragma unroll
        for (int n = 0; n < 4; ++n) {
            const int cl  = wn * 32 + n * 8 + tt * 2;
            const float b0 = sbias[cl], b1 = sbias[cl + 1];
            float x0 = fmaxf(acc[m][n][0] + b0, 0.0f);
            float x1 = fmaxf(acc[m][n][1] + b1, 0.0f);
            float x2 = fmaxf(acc[m][n][2] + b0, 0.0f);
            float x3 = fmaxf(acc[m][n][3] + b1, 0.0f);
            sp  += (x0 + x1) + (x2 + x3);
            cnt += (x0 > 0.0f) + (x1 > 0.0f) + (x2 > 0.0f) + (x3 > 0.0f);
            float* p0 = out + FEATS_OFF + ((long long)l * BNUM + r0) * FNUM + n0 + cl;
            float* p1 = out + FEATS_OFF + ((long long)l * BNUM + r0 + 8) * FNUM + n0 + cl;
            *(float2*)p0 = make_float2(x0, x1);
            *(float2*)p1 = make_float2(x2, x3);
        }
    }
#pragma unroll
    for (int o = 16; o > 0; o >>= 1) {
        sp  += __shfl_down_sync(0xffffffffu, sp, o);
        cnt += __shfl_down_sync(0xffffffffu, cnt, o);
    }
    if (lane == 0) { s_sp[wid] = sp; s_cnt[wid] = cnt; }
    __syncthreads();
    if (tid == 0) {
        float tsp = 0.0f; int tc = 0;
        for (int w = 0; w < 8; ++w) { tsp += s_sp[w]; tc += s_cnt[w]; }
        atomicAdd(&g_sp_sum, (double)tsp);
        atomicAdd(&g_cnt[l], (unsigned long long)tc);
    }
}

// ---------------- decoder (128x128 tile, 256 threads, occ 2; t descending) ----------------
__global__ __launch_bounds__(256, 2) void decoder_mma(const float* __restrict__ feats,  // [L,B,F]
                                                      const float* __restrict__ dec_w,  // [P,D,F]
                                                      const float* __restrict__ tgt,    // [L,B,D]
                                                      float* __restrict__ out) {
    extern __shared__ uint32_t smraw[];
    __shared__ float s_sq[8];

    const int tid = threadIdx.x;
    const int bid = blockIdx.x;
    const int t   = 7 - (bid >> 6);
    const int rem = bid & 63;
    const int m0  = (rem >> 3) * 128;
    const int n0  = (rem & 7) * 128;
    const uint32_t smb = smem_u32(smraw);

    int aslot0, bslot0, gpc;
    prod_bases(tid, aslot0, bslot0, gpc);
    const int rbase = tid >> 4;

    const int s_lo = (t >= 2) ? (t - 2) : 0;
    const int nseg = t - s_lo + 1;
    const int NC   = nseg * 256;

    float acc[4][4][4];
#pragma unroll
    for (int m = 0; m < 4; ++m)
#pragma unroll
        for (int n = 0; n < 4; ++n)
#pragma unroll
            for (int q = 0; q < 4; ++q) acc[m][n][q] = 0.0f;

    const int lane = tid & 31, wid = tid >> 5;
    const int wm = wid >> 2, wn = wid & 3;

    const float* Ap = nullptr;
    const float* Bp = nullptr;

    for (int c = 0; c < NC; ++c) {
        if ((c & 255) == 0) {   // segment boundary: recompute base pointers
            const int s    = s_lo + (c >> 8);
            const int pb   = ((s <= 5) ? (3 * s) : (2 * s + 6)) + (t - s);
            Ap = feats + ((long long)s * BNUM + m0 + rbase) * FNUM + gpc;
            Bp = dec_w + ((long long)pb * DNUM + n0 + rbase) * FNUM + gpc;
        }
        uint32_t* st = smraw + (c & 1) * 6144;
#pragma unroll
        for (int i = 0; i < 8; ++i) {
            float2 v = *(const float2*)(Ap + i * 16 * FNUM);
            st[aslot0 + 256 * i] = pack16(v.x, v.y);
        }
#pragma unroll
        for (int i = 0; i < 8; ++i) {
            float2 v = *(const float2*)(Bp + i * 16 * FNUM);
            uint32_t h, lo;
            split2(v.x, v.y, h, lo);
            st[2048 + bslot0 + 256 * i] = h;
            st[4096 + bslot0 + 256 * i] = lo;
        }
        Ap += KC;
        Bp += KC;
        __syncthreads();
        consume_chunk2(smb + (c & 1) * 24576, lane, wm, wn, acc);
    }

    const int g = lane >> 2, tt = lane & 3;

    float sq = 0.0f;
#pragma unroll
    for (int m = 0; m < 4; ++m) {
        const int r0 = m0 + wm * 64 + m * 16 + g;
#pragma unroll
        for (int n = 0; n < 4; ++n) {
            const int col = n0 + wn * 32 + n * 8 + tt * 2;
            const long long row0 = (long long)t * BNUM + r0;
            const long long row1 = row0 + 8;
            float2 t0 = *(const float2*)(tgt + row0 * DNUM + col);
            float2 t1 = *(const float2*)(tgt + row1 * DNUM + col);
            const float v0 = acc[m][n][0], v1 = acc[m][n][1];
            const float v2 = acc[m][n][2], v3 = acc[m][n][3];
            float d0 = v0 - t0.x, d1 = v1 - t0.y, d2 = v2 - t1.x, d3 = v3 - t1.y;
            sq = fmaf(d0, d0, sq); sq = fmaf(d1, d1, sq);
            sq = fmaf(d2, d2, sq); sq = fmaf(d3, d3, sq);
            *(float2*)(out + row0 * DNUM + col) = make_float2(v0, v1);
            *(float2*)(out + row1 * DNUM + col) = make_float2(v2, v3);
        }
    }
#pragma unroll
    for (int o = 16; o > 0; o >>= 1) sq += __shfl_down_sync(0xffffffffu, sq, o);
    if (lane == 0) s_sq[wid] = sq;
    __syncthreads();
    if (tid == 0) {
        float tsq = 0.0f;
        for (int w = 0; w < 8; ++w) tsq += s_sq[w];
        atomicAdd(&g_sq_sum, (double)tsq);
    }
}

// ---------------- finalize scalars ----------------
__global__ void finalize_kernel(float* __restrict__ out) {
    const int tid = threadIdx.x;
    if (tid == 0) {
        double rl = g_sq_sum / ((double)LNUM * (double)BNUM * (double)DNUM);
        double sl = 1e-4 * (g_sp_sum / ((double)LNUM * (double)BNUM * (double)FNUM));
        out[LOSS_OFF + 0] = (float)(rl + sl);
        out[LOSS_OFF + 1] = (float)rl;
        out[LOSS_OFF + 2] = (float)sl;
    }
    if (tid < LNUM) out[LOSS_OFF + 3 + tid] = (float)((double)g_cnt[tid] / (double)BNUM);
}

// ---------------- entry point ----------------
#define SMEM_2T (2 * 6144 * 4)   // 48 KB (two 24 KB stages)

extern "C" void kernel_launch(void* const* d_in, const int* in_sizes, int n_in,
                              void* d_out, int out_size) {
    (void)in_sizes; (void)n_in; (void)out_size;
    const float* resid   = (const float*)d_in[0];
    const float* targets = (const float*)d_in[1];
    const float* enc_w   = (const float*)d_in[2];
    const float* enc_b   = (const float*)d_in[3];
    const float* dec_w   = (const float*)d_in[4];
    float* out = (float*)d_out;

    static bool attr_done = false;
    if (!attr_done) {
        cudaFuncSetAttribute(encoder_mma, cudaFuncAttributeMaxDynamicSharedMemorySize, SMEM_2T);
        cudaFuncSetAttribute(decoder_mma, cudaFuncAttributeMaxDynamicSharedMemorySize, SMEM_2T);
        attr_done = true;
    }

    init_acc_kernel<<<1, 1>>>();

    dim3 genc(FNUM / 128, BNUM / 128, LNUM);  // (64, 8, 8)
    encoder_mma<<<genc, 256, SMEM_2T>>>(resid, enc_w, enc_b, out);

    decoder_mma<<<512, 256, SMEM_2T>>>(out + FEATS_OFF, dec_w, targets, out);

    finalize_kernel<<<1, 32>>>(out);
}